// round 4
// baseline (speedup 1.0000x reference)
#include <cuda_runtime.h>

// Problem constants
#define NBATCH 64
#define TLEN   2048
#define INDIM  8
#define CCH    2
#define MDIM   10
#define TSTEPS (TLEN - 1)          // 2047 increments
#define NCHAINS (NBATCH * CCH)     // 128 independent ordered products

// Parallel decomposition
#define SPC    51                  // segments per chain (divisible by 3)
#define WPC    (SPC / 3)           // 17 warps per chain (3 segments per warp)
#define SEGLEN 41                  // ceil(2047/51)
#define NGROUPS_BLK 24             // 8 warps/block * 3 groups/warp
#define PAD    104                 // padded matrix slot (floats), 8B-multiple
#define THETA  0.8f

// Scratch: per-segment partial products (128 * 51 * 100 floats = 2.6 MB)
__device__ __align__(16) float g_partials[NCHAINS * SPC * MDIM * MDIM];

// Row-matmul: out[0..9] = a(row) @ B (B row-major 10x10 in shared), float2 reads.
__device__ __forceinline__ void mm_row(const float a[MDIM], const float* B, float out[MDIM]) {
#pragma unroll
    for (int c = 0; c < MDIM; ++c) out[c] = 0.f;
#pragma unroll
    for (int k = 0; k < MDIM; ++k) {
        float av = a[k];
        const float2* Bk = reinterpret_cast<const float2*>(B + k * MDIM);
#pragma unroll
        for (int c2 = 0; c2 < 5; ++c2) {
            float2 b = Bk[c2];
            out[2 * c2]     = fmaf(av, b.x, out[2 * c2]);
            out[2 * c2 + 1] = fmaf(av, b.y, out[2 * c2 + 1]);
        }
    }
}

__device__ __forceinline__ void st_row(float* dst, const float v[MDIM]) {
    float2* d2 = reinterpret_cast<float2*>(dst);
#pragma unroll
    for (int c2 = 0; c2 < 5; ++c2) d2[c2] = make_float2(v[2 * c2], v[2 * c2 + 1]);
}

// ---------------------------------------------------------------------------
// Phase A: each 10-lane group walks one time-segment of one chain.
// Per step: build skew G, scale (||G||inf <= THETA), exp(G) = C(S) + G*D(S)
// (degree-9 Taylor via even/odd split, 5 matmuls), square s times, P = P @ E.
// ---------------------------------------------------------------------------
__global__ __launch_bounds__(256, 2)
void phaseA_kernel(const float* __restrict__ x, const float* __restrict__ A) {
    __shared__ __align__(16) float skew[CCH * INDIM * MDIM * MDIM]; // 1600
    __shared__ __align__(16) float bufA[NGROUPS_BLK][PAD];
    __shared__ __align__(16) float bufB[NGROUPS_BLK][PAD];
    __shared__ float dxsh[NGROUPS_BLK][INDIM];
    __shared__ float rssh[NGROUPS_BLK][16];

    const int tid = threadIdx.x;

    // skew = A - A^T (per c,i), cooperative load
    for (int idx = tid; idx < CCH * INDIM * MDIM * MDIM; idx += blockDim.x) {
        int k  = idx % MDIM;
        int j  = (idx / MDIM) % MDIM;
        int ci = idx / (MDIM * MDIM);
        skew[idx] = A[ci * MDIM * MDIM + j * MDIM + k] - A[ci * MDIM * MDIM + k * MDIM + j];
    }
    __syncthreads();

    const int warpInBlk = tid >> 5;
    const int lane = tid & 31;
    const int g = lane / MDIM;            // 0..2 matrix groups, 3 = idle lanes
    const int r = lane % MDIM;            // row owned by this thread
    const bool active = (g < 3);
    const int gg = active ? (warpInBlk * 3 + g) : (warpInBlk * 3); // clamp idle reads
    const int warpGlobal = blockIdx.x * (blockDim.x >> 5) + warpInBlk;
    const int chain = warpGlobal / WPC;   // 0..127
    const int wInChain = warpGlobal % WPC;
    const int seg = wInChain * 3 + (active ? g : 0);
    const int n   = chain >> 1;
    const int cch = chain & 1;
    const int t0 = seg * SEGLEN;
    const int tend = min(t0 + SEGLEN, TSTEPS);
    const float* skc = skew + cch * (INDIM * MDIM * MDIM);

    float P[MDIM];
#pragma unroll
    for (int k = 0; k < MDIM; ++k) P[k] = (k == r) ? 1.f : 0.f;

    for (int it = 0; it < SEGLEN; ++it) {
        int t = t0 + it;
        bool doStep = active && (t < tend);

        // path increment dX[t] = x[t+1]-x[t]
        if (doStep && r < INDIM) {
            const float* xr = x + (n * TLEN + t) * INDIM + r;
            dxsh[gg][r] = xr[INDIM] - xr[0];
        }
        __syncwarp();
        float dx[INDIM];
#pragma unroll
        for (int i = 0; i < INDIM; ++i) dx[i] = dxsh[gg][i];

        // G row: G[r,k] = sum_i dx[i]*skew[c,i,r,k]
        float G[MDIM];
#pragma unroll
        for (int k = 0; k < MDIM; ++k) G[k] = 0.f;
#pragma unroll
        for (int i = 0; i < INDIM; ++i) {
            const float2* sk2 = reinterpret_cast<const float2*>(skc + i * 100 + r * MDIM);
#pragma unroll
            for (int c2 = 0; c2 < 5; ++c2) {
                float2 sv = sk2[c2];
                G[2 * c2]     = fmaf(dx[i], sv.x, G[2 * c2]);
                G[2 * c2 + 1] = fmaf(dx[i], sv.y, G[2 * c2 + 1]);
            }
        }

        // ||G||inf, per-matrix scaling exponent s
        float rs = 0.f;
#pragma unroll
        for (int k = 0; k < MDIM; ++k) rs += fabsf(G[k]);
        if (active) rssh[gg][r] = rs;
        __syncwarp();
        float nrm = 0.f;
#pragma unroll
        for (int k = 0; k < MDIM; ++k) nrm = fmaxf(nrm, rssh[gg][k]);
        int s = 0;
        if (doStep && nrm > THETA) {
            s = (int)ceilf(log2f(nrm * (1.0f / THETA)));
            if (s < 0) s = 0;
            if (s > 24) s = 24;
            float sc = exp2f((float)(-s));
#pragma unroll
            for (int k = 0; k < MDIM; ++k) G[k] *= sc;
        }

        // S = G*G
        if (doStep) st_row(bufA[gg] + r * MDIM, G);
        __syncwarp();
        float S[MDIM];
        mm_row(G, bufA[gg], S);
        if (doStep) st_row(bufB[gg] + r * MDIM, S);
        __syncwarp();
        // S2 = S*S
        float S2[MDIM];
        mm_row(S, bufB[gg], S2);

        // even tail: TC = S2 @ (S/720 + S2/40320); C = I + S/2 + S2/24 + TC
        float tmp[MDIM];
#pragma unroll
        for (int k = 0; k < MDIM; ++k) tmp[k] = S[k] * (1.f / 720.f) + S2[k] * (1.f / 40320.f);
        if (doStep) st_row(bufA[gg] + r * MDIM, tmp);
        __syncwarp();
        float TC[MDIM];
        mm_row(S2, bufA[gg], TC);
        float Cc[MDIM];
#pragma unroll
        for (int k = 0; k < MDIM; ++k)
            Cc[k] = ((k == r) ? 1.f : 0.f) + S[k] * 0.5f + S2[k] * (1.f / 24.f) + TC[k];

        // odd tail: TD = S2 @ (S/5040 + S2/362880); D = I + S/6 + S2/120 + TD
#pragma unroll
        for (int k = 0; k < MDIM; ++k) tmp[k] = S[k] * (1.f / 5040.f) + S2[k] * (1.f / 362880.f);
        __syncwarp();   // TC readers done with bufA
        if (doStep) st_row(bufA[gg] + r * MDIM, tmp);
        __syncwarp();
        float TD[MDIM];
        mm_row(S2, bufA[gg], TD);
        float Dd[MDIM];
#pragma unroll
        for (int k = 0; k < MDIM; ++k)
            Dd[k] = ((k == r) ? 1.f : 0.f) + S[k] * (1.f / 6.f) + S2[k] * (1.f / 120.f) + TD[k];

        // E = C + G @ D   (degree-9 Taylor of exp(G))
        __syncwarp();
        if (doStep) st_row(bufA[gg] + r * MDIM, Dd);
        __syncwarp();
        float E[MDIM];
        mm_row(G, bufA[gg], E);
#pragma unroll
        for (int k = 0; k < MDIM; ++k) E[k] += Cc[k];

        // squarings (rare: s=0 typical)
        int smax = s;
#pragma unroll
        for (int off = 16; off; off >>= 1)
            smax = max(smax, __shfl_xor_sync(0xffffffffu, smax, off));
        for (int q = 0; q < smax; ++q) {
            __syncwarp();
            if (q < s) st_row(bufA[gg] + r * MDIM, E);
            __syncwarp();
            if (q < s) {
                float E2[MDIM];
                mm_row(E, bufA[gg], E2);
#pragma unroll
                for (int k = 0; k < MDIM; ++k) E[k] = E2[k];
            }
        }

        // ordered chain: P = P @ E
        __syncwarp();
        if (doStep) st_row(bufA[gg] + r * MDIM, E);
        __syncwarp();
        if (doStep) {
            float Pn[MDIM];
            mm_row(P, bufA[gg], Pn);
#pragma unroll
            for (int k = 0; k < MDIM; ++k) P[k] = Pn[k];
        }
    }

    if (active) {
        float* dst = g_partials + (chain * SPC + seg) * 100 + r * MDIM;
        float2* d2 = reinterpret_cast<float2*>(dst);
#pragma unroll
        for (int c2 = 0; c2 < 5; ++c2) d2[c2] = make_float2(P[2 * c2], P[2 * c2 + 1]);
    }
}

// ---------------------------------------------------------------------------
// Phase B: per chain, multiply the 51 segment partials in order (one warp each).
// ---------------------------------------------------------------------------
__global__ __launch_bounds__(256)
void phaseB_kernel(float* __restrict__ out) {
    __shared__ __align__(16) float buf[8][PAD];
    const int tid = threadIdx.x, warp = tid >> 5, lane = tid & 31;
    const int r = lane % MDIM;
    const bool active = lane < MDIM;
    const int chain = blockIdx.x * 8 + warp;
    const float* base = g_partials + chain * SPC * 100;

    float P[MDIM];
    if (active) {
        const float2* s2p = reinterpret_cast<const float2*>(base + r * MDIM);
#pragma unroll
        for (int c2 = 0; c2 < 5; ++c2) {
            float2 v = s2p[c2];
            P[2 * c2] = v.x; P[2 * c2 + 1] = v.y;
        }
    }
    for (int segi = 1; segi < SPC; ++segi) {
        __syncwarp();
        if (active) {
            const float2* s2p = reinterpret_cast<const float2*>(base + segi * 100 + r * MDIM);
            float2* d2 = reinterpret_cast<float2*>(buf[warp] + r * MDIM);
#pragma unroll
            for (int c2 = 0; c2 < 5; ++c2) d2[c2] = s2p[c2];
        }
        __syncwarp();
        if (active) {
            float Pn[MDIM];
            mm_row(P, buf[warp], Pn);
#pragma unroll
            for (int k = 0; k < MDIM; ++k) P[k] = Pn[k];
        }
    }
    if (active) {
        float2* d2 = reinterpret_cast<float2*>(out + chain * 100 + r * MDIM);
#pragma unroll
        for (int c2 = 0; c2 < 5; ++c2) d2[c2] = make_float2(P[2 * c2], P[2 * c2 + 1]);
    }
}

extern "C" void kernel_launch(void* const* d_in, const int* in_sizes, int n_in,
                              void* d_out, int out_size) {
    (void)in_sizes; (void)n_in; (void)out_size;
    const float* x = (const float*)d_in[0];   // (64, 2048, 8) f32
    const float* A = (const float*)d_in[1];   // (2, 8, 10, 10) f32
    float* out = (float*)d_out;               // (64, 2, 10, 10) f32

    // 128 chains * 17 warps = 2176 warps -> 272 blocks of 8 warps
    phaseA_kernel<<<272, 256>>>(x, A);
    phaseB_kernel<<<16, 256>>>(out);
}

// round 5
// speedup vs baseline: 1.0923x; 1.0923x over previous
#include <cuda_runtime.h>

// Problem constants
#define NBATCH 64
#define TLEN   2048
#define INDIM  8
#define CCH    2
#define MDIM   10
#define TSTEPS (TLEN - 1)          // 2047 increments
#define NCHAINS (NBATCH * CCH)     // 128 independent ordered products

// Parallel decomposition
#define SPC    81                  // segments per chain (divisible by 3)
#define WPC    (SPC / 3)           // 27 warps per chain (3 segments per warp)
#define SEGLEN 26                  // ceil(2047/81)
#define NGROUPS_BLK 24             // 8 warps/block * 3 groups/warp
#define PAD    104                 // padded matrix slot (floats), 8B-multiple
#define THETA  0.8f

// Scratch: per-segment partial products (128 * 81 * 100 floats = 4.15 MB, L2-resident)
__device__ __align__(16) float g_partials[NCHAINS * SPC * MDIM * MDIM];

// Row-matmul: out[0..9] = a(row) @ B (B row-major 10x10 in shared), float2 reads.
__device__ __forceinline__ void mm_row(const float a[MDIM], const float* B, float out[MDIM]) {
#pragma unroll
    for (int c = 0; c < MDIM; ++c) out[c] = 0.f;
#pragma unroll
    for (int k = 0; k < MDIM; ++k) {
        float av = a[k];
        const float2* Bk = reinterpret_cast<const float2*>(B + k * MDIM);
#pragma unroll
        for (int c2 = 0; c2 < 5; ++c2) {
            float2 b = Bk[c2];
            out[2 * c2]     = fmaf(av, b.x, out[2 * c2]);
            out[2 * c2 + 1] = fmaf(av, b.y, out[2 * c2 + 1]);
        }
    }
}

__device__ __forceinline__ void st_row(float* dst, const float v[MDIM]) {
    float2* d2 = reinterpret_cast<float2*>(dst);
#pragma unroll
    for (int c2 = 0; c2 < 5; ++c2) d2[c2] = make_float2(v[2 * c2], v[2 * c2 + 1]);
}

// ---------------------------------------------------------------------------
// Phase A: each 10-lane group walks one time-segment of one chain.
// exp(G) = C(S) + G*D(S), S=G^2, via S3/S4 basis:
//   C = I + S/2 + S2/24 + S3/720 + S4/40320
//   D = I + S/6 + S2/120 + S3/5040 + S4/362880
// 6 matmuls/step (S, S2, S3, S4, G@D, P@E), 7 syncwarps/step.
// ---------------------------------------------------------------------------
__global__ __launch_bounds__(256, 3)
void phaseA_kernel(const float* __restrict__ x, const float* __restrict__ A) {
    __shared__ __align__(16) float skew[CCH * INDIM * MDIM * MDIM]; // 1600
    __shared__ __align__(16) float bufA[NGROUPS_BLK][PAD];
    __shared__ __align__(16) float bufB[NGROUPS_BLK][PAD];
    __shared__ float dxsh[NGROUPS_BLK][INDIM];
    __shared__ float rssh[NGROUPS_BLK][16];

    const int tid = threadIdx.x;

    // skew = A - A^T (per c,i), cooperative load
    for (int idx = tid; idx < CCH * INDIM * MDIM * MDIM; idx += blockDim.x) {
        int k  = idx % MDIM;
        int j  = (idx / MDIM) % MDIM;
        int ci = idx / (MDIM * MDIM);
        skew[idx] = A[ci * MDIM * MDIM + j * MDIM + k] - A[ci * MDIM * MDIM + k * MDIM + j];
    }
    __syncthreads();

    const int warpInBlk = tid >> 5;
    const int lane = tid & 31;
    const int g = lane / MDIM;            // 0..2 matrix groups, 3 = idle lanes
    const int r = lane % MDIM;            // row owned by this thread
    const bool active = (g < 3);
    const int gg = active ? (warpInBlk * 3 + g) : (warpInBlk * 3); // clamp idle reads
    const int warpGlobal = blockIdx.x * (blockDim.x >> 5) + warpInBlk;
    const int chain = warpGlobal / WPC;   // 0..127
    const int wInChain = warpGlobal % WPC;
    const int seg = wInChain * 3 + (active ? g : 0);
    const int n   = chain >> 1;
    const int cch = chain & 1;
    const int t0 = seg * SEGLEN;
    const int tend = min(t0 + SEGLEN, TSTEPS);
    const float* skc = skew + cch * (INDIM * MDIM * MDIM);

    float P[MDIM];
#pragma unroll
    for (int k = 0; k < MDIM; ++k) P[k] = (k == r) ? 1.f : 0.f;

    for (int it = 0; it < SEGLEN; ++it) {
        int t = t0 + it;
        bool doStep = active && (t < tend);

        // path increment dX[t] = x[t+1]-x[t]
        if (doStep && r < INDIM) {
            const float* xr = x + (n * TLEN + t) * INDIM + r;
            dxsh[gg][r] = xr[INDIM] - xr[0];
        }
        __syncwarp();

        // G row: G[r,k] = sum_i dx[i]*skew[c,i,r,k]  (dx read from smem, saves regs)
        float G[MDIM];
#pragma unroll
        for (int k = 0; k < MDIM; ++k) G[k] = 0.f;
#pragma unroll
        for (int i = 0; i < INDIM; ++i) {
            float av = dxsh[gg][i];
            const float2* sk2 = reinterpret_cast<const float2*>(skc + i * 100 + r * MDIM);
#pragma unroll
            for (int c2 = 0; c2 < 5; ++c2) {
                float2 sv = sk2[c2];
                G[2 * c2]     = fmaf(av, sv.x, G[2 * c2]);
                G[2 * c2 + 1] = fmaf(av, sv.y, G[2 * c2 + 1]);
            }
        }

        // ||G||inf, per-matrix scaling exponent s
        float rs = 0.f;
#pragma unroll
        for (int k = 0; k < MDIM; ++k) rs += fabsf(G[k]);
        if (active) rssh[gg][r] = rs;
        __syncwarp();
        float nrm = 0.f;
#pragma unroll
        for (int k = 0; k < MDIM; ++k) nrm = fmaxf(nrm, rssh[gg][k]);
        int s = 0;
        if (doStep && nrm > THETA) {
            s = (int)ceilf(log2f(nrm * (1.0f / THETA)));
            if (s < 0) s = 0;
            if (s > 24) s = 24;
            float sc = exp2f((float)(-s));
#pragma unroll
            for (int k = 0; k < MDIM; ++k) G[k] *= sc;
        }

        // S = G@G
        if (doStep) st_row(bufA[gg] + r * MDIM, G);
        __syncwarp();
        float S[MDIM];
        mm_row(G, bufA[gg], S);

        // S2 = S@S and S3 = S2@S (both use S staged in bufB; no extra sync)
        if (doStep) st_row(bufB[gg] + r * MDIM, S);
        __syncwarp();
        float S2[MDIM];
        mm_row(S, bufB[gg], S2);
        float S3[MDIM];
        mm_row(S2, bufB[gg], S3);

        // S4 = S2@S2 (S2 staged in bufA; WAR safe: bufA(G) reads completed
        // before the S-stage syncwarp on every lane)
        if (doStep) st_row(bufA[gg] + r * MDIM, S2);
        __syncwarp();
        float S4[MDIM];
        mm_row(S2, bufA[gg], S4);

        // D = I + S/6 + S2/120 + S3/5040 + S4/362880 -> straight into bufB
        if (doStep) {
#pragma unroll
            for (int k = 0; k < MDIM; ++k) {
                float d = ((k == r) ? 1.f : 0.f) + S[k] * (1.f / 6.f) + S2[k] * (1.f / 120.f)
                        + S3[k] * (1.f / 5040.f) + S4[k] * (1.f / 362880.f);
                bufB[gg][r * MDIM + k] = d;
            }
        }
        __syncwarp();

        // C = I + S/2 + S2/24 + S3/720 + S4/40320 (registers); E = C + G@D
        float E[MDIM];
        mm_row(G, bufB[gg], E);
#pragma unroll
        for (int k = 0; k < MDIM; ++k)
            E[k] += ((k == r) ? 1.f : 0.f) + S[k] * 0.5f + S2[k] * (1.f / 24.f)
                  + S3[k] * (1.f / 720.f) + S4[k] * (1.f / 40320.f);

        // squarings (rare: s=0 typical)
        int smax = s;
#pragma unroll
        for (int off = 16; off; off >>= 1)
            smax = max(smax, __shfl_xor_sync(0xffffffffu, smax, off));
        for (int q = 0; q < smax; ++q) {
            __syncwarp();
            if (q < s) st_row(bufA[gg] + r * MDIM, E);
            __syncwarp();
            if (q < s) {
                float E2[MDIM];
                mm_row(E, bufA[gg], E2);
#pragma unroll
                for (int k = 0; k < MDIM; ++k) E[k] = E2[k];
            }
        }

        // ordered chain: P = P @ E
        __syncwarp();
        if (doStep) st_row(bufA[gg] + r * MDIM, E);
        __syncwarp();
        if (doStep) {
            float Pn[MDIM];
            mm_row(P, bufA[gg], Pn);
#pragma unroll
            for (int k = 0; k < MDIM; ++k) P[k] = Pn[k];
        }
    }

    if (active) {
        float* dst = g_partials + (chain * SPC + seg) * 100 + r * MDIM;
        float2* d2 = reinterpret_cast<float2*>(dst);
#pragma unroll
        for (int c2 = 0; c2 < 5; ++c2) d2[c2] = make_float2(P[2 * c2], P[2 * c2 + 1]);
    }
}

// ---------------------------------------------------------------------------
// Phase B: one block per chain. Bulk-load all 81 partials to SMEM (coalesced
// float4), then warp 0 runs 3 parallel serial products of 27 each (no syncs,
// no staging: A operand in registers, B operand read straight from SMEM),
// then combines the 3 partials in order.
// ---------------------------------------------------------------------------
__global__ __launch_bounds__(128)
void phaseB_kernel(float* __restrict__ out) {
    __shared__ __align__(16) float mats[SPC * 100];   // 8100 floats = 32.4KB
    __shared__ __align__(16) float comb[3 * 100];

    const int tid = threadIdx.x;
    const int chain = blockIdx.x;

    // coalesced bulk load: 8100 floats = 2025 float4
    {
        const float4* src = reinterpret_cast<const float4*>(g_partials + chain * (SPC * 100));
        float4* dst = reinterpret_cast<float4*>(mats);
        for (int i = tid; i < (SPC * 100) / 4; i += 128) dst[i] = src[i];
    }
    __syncthreads();

    if (tid < 32) {
        const int lane = tid;
        const int g = lane / MDIM;        // 3 groups of 10; lanes 30,31 idle
        const int r = lane % MDIM;
        const bool active = (g < 3);
        const int s0 = active ? g * WPC : 0;

        // P = mats[s0]
        float P[MDIM];
        {
            const float2* m2 = reinterpret_cast<const float2*>(mats + s0 * 100 + r * MDIM);
#pragma unroll
            for (int c2 = 0; c2 < 5; ++c2) {
                float2 v = m2[c2];
                P[2 * c2] = v.x; P[2 * c2 + 1] = v.y;
            }
        }
        // serial product over own 27 segments: P = P @ mats[s]
        for (int si = 1; si < WPC; ++si) {
            float Pn[MDIM];
            mm_row(P, mats + (s0 + si) * 100, Pn);
#pragma unroll
            for (int k = 0; k < MDIM; ++k) P[k] = Pn[k];
        }

        // stage the 3 group partials, then group 0 combines in order
        __syncwarp();
        if (active) st_row(comb + g * 100 + r * MDIM, P);
        __syncwarp();
        if (g == 0) {
            float T[MDIM];
            mm_row(P, comb + 100, T);          // P0 @ P1
            float T2[MDIM];
            mm_row(T, comb + 200, T2);         // @ P2
            float2* d2 = reinterpret_cast<float2*>(out + chain * 100 + r * MDIM);
#pragma unroll
            for (int c2 = 0; c2 < 5; ++c2) d2[c2] = make_float2(T2[2 * c2], T2[2 * c2 + 1]);
        }
    }
}

extern "C" void kernel_launch(void* const* d_in, const int* in_sizes, int n_in,
                              void* d_out, int out_size) {
    (void)in_sizes; (void)n_in; (void)out_size;
    const float* x = (const float*)d_in[0];   // (64, 2048, 8) f32
    const float* A = (const float*)d_in[1];   // (2, 8, 10, 10) f32
    float* out = (float*)d_out;               // (64, 2, 10, 10) f32

    // 128 chains * 27 warps = 3456 warps -> 432 blocks of 8 warps (one wave @ 3 blk/SM)
    phaseA_kernel<<<432, 256>>>(x, A);
    phaseB_kernel<<<NCHAINS, 128>>>(out);
}

// round 14
// speedup vs baseline: 1.1217x; 1.0269x over previous
#include <cuda_runtime.h>

// Problem constants
#define NBATCH 64
#define TLEN   2048
#define INDIM  8
#define CCH    2
#define MDIM   10
#define TSTEPS (TLEN - 1)          // 2047 increments
#define NCHAINS (NBATCH * CCH)     // 128 independent ordered products

// Parallel decomposition
#define SPC    81                  // segments per chain (divisible by 3)
#define WPC    (SPC / 3)           // 27 warps per chain (3 segments per warp)
#define SEGLEN 26                  // ceil(2047/81)
#define NGROUPS_BLK 24             // 8 warps/block * 3 groups/warp
#define PAD    104                 // padded matrix slot (floats), 8B-multiple
#define THETA  0.8f

// Scratch: per-segment partial products (128 * 81 * 100 floats = 4.15 MB, L2-resident)
__device__ __align__(16) float g_partials[NCHAINS * SPC * MDIM * MDIM];

// ---------------------------------------------------------------------------
// f32x2 packed row-matmul: out = a(row) @ B, B row-major 10x10 in shared.
// Uses Blackwell fma.rn.f32x2 (FFMA2): 50 packed FMAs instead of 100 scalar.
// ---------------------------------------------------------------------------
__device__ __forceinline__ void mm_row(const float a[MDIM], const float* B, float out[MDIM]) {
    unsigned long long acc0 = 0ull, acc1 = 0ull, acc2 = 0ull, acc3 = 0ull, acc4 = 0ull;
#pragma unroll
    for (int k = 0; k < MDIM; ++k) {
        unsigned int au = __float_as_uint(a[k]);
        unsigned long long av;
        asm("mov.b64 %0, {%1, %1};" : "=l"(av) : "r"(au));
        const unsigned long long* Bk = reinterpret_cast<const unsigned long long*>(B + k * MDIM);
        unsigned long long b0 = Bk[0], b1 = Bk[1], b2 = Bk[2], b3 = Bk[3], b4 = Bk[4];
        asm("fma.rn.f32x2 %0, %1, %2, %0;" : "+l"(acc0) : "l"(av), "l"(b0));
        asm("fma.rn.f32x2 %0, %1, %2, %0;" : "+l"(acc1) : "l"(av), "l"(b1));
        asm("fma.rn.f32x2 %0, %1, %2, %0;" : "+l"(acc2) : "l"(av), "l"(b2));
        asm("fma.rn.f32x2 %0, %1, %2, %0;" : "+l"(acc3) : "l"(av), "l"(b3));
        asm("fma.rn.f32x2 %0, %1, %2, %0;" : "+l"(acc4) : "l"(av), "l"(b4));
    }
    asm("mov.b64 {%0, %1}, %2;" : "=f"(out[0]), "=f"(out[1]) : "l"(acc0));
    asm("mov.b64 {%0, %1}, %2;" : "=f"(out[2]), "=f"(out[3]) : "l"(acc1));
    asm("mov.b64 {%0, %1}, %2;" : "=f"(out[4]), "=f"(out[5]) : "l"(acc2));
    asm("mov.b64 {%0, %1}, %2;" : "=f"(out[6]), "=f"(out[7]) : "l"(acc3));
    asm("mov.b64 {%0, %1}, %2;" : "=f"(out[8]), "=f"(out[9]) : "l"(acc4));
}

__device__ __forceinline__ void st_row(float* dst, const float v[MDIM]) {
    float2* d2 = reinterpret_cast<float2*>(dst);
#pragma unroll
    for (int c2 = 0; c2 < 5; ++c2) d2[c2] = make_float2(v[2 * c2], v[2 * c2 + 1]);
}

// ---------------------------------------------------------------------------
// Phase A: each 10-lane group walks one time-segment of one chain.
// exp(G) = C(S) + G*D(S), S=G^2 (Paterson-Stockmeyer, degree 9):
//   C = I + S/2 + S2/24 + S2@(S/720 + S2/40320)
//   D = I + S/6 + S2/120 + S2@(S/5040 + S2/362880)
// Sequenced for <=~50 live floats (no spills at 85-reg cap, 3 blocks/SM).
// ---------------------------------------------------------------------------
__global__ __launch_bounds__(256, 3)
void phaseA_kernel(const float* __restrict__ x, const float* __restrict__ A) {
    __shared__ __align__(16) float skew[CCH * INDIM * MDIM * MDIM]; // 1600
    __shared__ __align__(16) float bufA[NGROUPS_BLK][PAD];
    __shared__ __align__(16) float bufB[NGROUPS_BLK][PAD];
    __shared__ float dxsh[NGROUPS_BLK][INDIM];
    __shared__ float rssh[NGROUPS_BLK][16];

    const int tid = threadIdx.x;

    // skew = A - A^T (per c,i), cooperative load
    for (int idx = tid; idx < CCH * INDIM * MDIM * MDIM; idx += blockDim.x) {
        int k  = idx % MDIM;
        int j  = (idx / MDIM) % MDIM;
        int ci = idx / (MDIM * MDIM);
        skew[idx] = A[ci * MDIM * MDIM + j * MDIM + k] - A[ci * MDIM * MDIM + k * MDIM + j];
    }
    __syncthreads();

    const int warpInBlk = tid >> 5;
    const int lane = tid & 31;
    const int g = lane / MDIM;            // 0..2 matrix groups, 3 = idle lanes
    const int r = lane % MDIM;            // row owned by this thread
    const bool active = (g < 3);
    const int gg = active ? (warpInBlk * 3 + g) : (warpInBlk * 3); // clamp idle reads
    const int warpGlobal = blockIdx.x * (blockDim.x >> 5) + warpInBlk;
    const int chain = warpGlobal / WPC;   // 0..127
    const int wInChain = warpGlobal % WPC;
    const int seg = wInChain * 3 + (active ? g : 0);
    const int n   = chain >> 1;
    const int cch = chain & 1;
    const int t0 = seg * SEGLEN;
    const int tend = min(t0 + SEGLEN, TSTEPS);
    const float* skc = skew + cch * (INDIM * MDIM * MDIM);

    float P[MDIM];
#pragma unroll
    for (int k = 0; k < MDIM; ++k) P[k] = (k == r) ? 1.f : 0.f;

    for (int it = 0; it < SEGLEN; ++it) {
        int t = t0 + it;
        bool doStep = active && (t < tend);

        // path increment dX[t] = x[t+1]-x[t]
        if (doStep && r < INDIM) {
            const float* xr = x + (n * TLEN + t) * INDIM + r;
            dxsh[gg][r] = xr[INDIM] - xr[0];
        }
        __syncwarp();

        // G row: G[r,k] = sum_i dx[i]*skew[c,i,r,k]  (FFMA2, dx from smem)
        float G[MDIM];
        {
            unsigned long long a0 = 0ull, a1 = 0ull, a2 = 0ull, a3 = 0ull, a4 = 0ull;
#pragma unroll
            for (int i = 0; i < INDIM; ++i) {
                unsigned int au = __float_as_uint(dxsh[gg][i]);
                unsigned long long av;
                asm("mov.b64 %0, {%1, %1};" : "=l"(av) : "r"(au));
                const unsigned long long* sk2 =
                    reinterpret_cast<const unsigned long long*>(skc + i * 100 + r * MDIM);
                unsigned long long b0 = sk2[0], b1 = sk2[1], b2 = sk2[2], b3 = sk2[3], b4 = sk2[4];
                asm("fma.rn.f32x2 %0, %1, %2, %0;" : "+l"(a0) : "l"(av), "l"(b0));
                asm("fma.rn.f32x2 %0, %1, %2, %0;" : "+l"(a1) : "l"(av), "l"(b1));
                asm("fma.rn.f32x2 %0, %1, %2, %0;" : "+l"(a2) : "l"(av), "l"(b2));
                asm("fma.rn.f32x2 %0, %1, %2, %0;" : "+l"(a3) : "l"(av), "l"(b3));
                asm("fma.rn.f32x2 %0, %1, %2, %0;" : "+l"(a4) : "l"(av), "l"(b4));
            }
            asm("mov.b64 {%0, %1}, %2;" : "=f"(G[0]), "=f"(G[1]) : "l"(a0));
            asm("mov.b64 {%0, %1}, %2;" : "=f"(G[2]), "=f"(G[3]) : "l"(a1));
            asm("mov.b64 {%0, %1}, %2;" : "=f"(G[4]), "=f"(G[5]) : "l"(a2));
            asm("mov.b64 {%0, %1}, %2;" : "=f"(G[6]), "=f"(G[7]) : "l"(a3));
            asm("mov.b64 {%0, %1}, %2;" : "=f"(G[8]), "=f"(G[9]) : "l"(a4));
        }

        // ||G||inf, per-matrix scaling exponent s
        float rs = 0.f;
#pragma unroll
        for (int k = 0; k < MDIM; ++k) rs += fabsf(G[k]);
        if (active) rssh[gg][r] = rs;
        __syncwarp();
        float nrm = 0.f;
#pragma unroll
        for (int k = 0; k < MDIM; ++k) nrm = fmaxf(nrm, rssh[gg][k]);
        int s = 0;
        if (doStep && nrm > THETA) {
            s = (int)ceilf(log2f(nrm * (1.0f / THETA)));
            if (s < 0) s = 0;
            if (s > 24) s = 24;
            float sc = exp2f((float)(-s));
#pragma unroll
            for (int k = 0; k < MDIM; ++k) G[k] *= sc;
        }

        // S = G@G
        if (doStep) st_row(bufA[gg] + r * MDIM, G);
        __syncwarp();
        float S[MDIM];
        mm_row(G, bufA[gg], S);

        // S2 = S@S
        if (doStep) st_row(bufB[gg] + r * MDIM, S);
        __syncwarp();
        float S2[MDIM];
        mm_row(S, bufB[gg], S2);

        // even tail staged: tmp = S/720 + S2/40320 -> bufA (G stage readers done)
        {
            float tmp[MDIM];
#pragma unroll
            for (int k = 0; k < MDIM; ++k)
                tmp[k] = S[k] * (1.f / 720.f) + S2[k] * (1.f / 40320.f);
            if (doStep) st_row(bufA[gg] + r * MDIM, tmp);
        }
        __syncwarp();
        // C = I + S/2 + S2/24 + S2@tmp   (kept in regs)
        float C[MDIM];
        mm_row(S2, bufA[gg], C);
#pragma unroll
        for (int k = 0; k < MDIM; ++k)
            C[k] += ((k == r) ? 1.f : 0.f) + S[k] * 0.5f + S2[k] * (1.f / 24.f);

        // odd tail: tmp = S/5040 + S2/362880 -> bufA (after C readers finish)
        __syncwarp();
        {
            float tmp[MDIM];
#pragma unroll
            for (int k = 0; k < MDIM; ++k)
                tmp[k] = S[k] * (1.f / 5040.f) + S2[k] * (1.f / 362880.f);
            if (doStep) st_row(bufA[gg] + r * MDIM, tmp);
        }
        __syncwarp();
        // D = I + S/6 + S2/120 + S2@tmp -> straight into bufB (S dead after this)
        {
            float D[MDIM];
            mm_row(S2, bufA[gg], D);
            if (doStep) {
#pragma unroll
                for (int k = 0; k < MDIM; ++k) {
                    float d = D[k] + ((k == r) ? 1.f : 0.f)
                            + S[k] * (1.f / 6.f) + S2[k] * (1.f / 120.f);
                    bufB[gg][r * MDIM + k] = d;
                }
            }
        }
        __syncwarp();

        // E = C + G@D
        float E[MDIM];
        mm_row(G, bufB[gg], E);
#pragma unroll
        for (int k = 0; k < MDIM; ++k) E[k] += C[k];

        // squarings (rare: s=0 typical)
        int smax = s;
#pragma unroll
        for (int off = 16; off; off >>= 1)
            smax = max(smax, __shfl_xor_sync(0xffffffffu, smax, off));
        for (int q = 0; q < smax; ++q) {
            __syncwarp();
            if (q < s) st_row(bufA[gg] + r * MDIM, E);
            __syncwarp();
            if (q < s) {
                float E2[MDIM];
                mm_row(E, bufA[gg], E2);
#pragma unroll
                for (int k = 0; k < MDIM; ++k) E[k] = E2[k];
            }
        }

        // ordered chain: P = P @ E
        __syncwarp();
        if (doStep) st_row(bufA[gg] + r * MDIM, E);
        __syncwarp();
        if (doStep) {
            float Pn[MDIM];
            mm_row(P, bufA[gg], Pn);
#pragma unroll
            for (int k = 0; k < MDIM; ++k) P[k] = Pn[k];
        }
    }

    if (active) {
        float* dst = g_partials + (chain * SPC + seg) * 100 + r * MDIM;
        float2* d2 = reinterpret_cast<float2*>(dst);
#pragma unroll
        for (int c2 = 0; c2 < 5; ++c2) d2[c2] = make_float2(P[2 * c2], P[2 * c2 + 1]);
    }
}

// ---------------------------------------------------------------------------
// Phase B: one block (128 thr) per chain. Bulk-load 81 partials into SMEM,
// 12 groups of 10 lanes each serially fold up to 7 adjacent segments, then
// pairwise tree 12->6->3->2->1. Critical path ~11 matmuls (was 29).
// ---------------------------------------------------------------------------
#define NGB 12            // groups in phase B
#define GPB 7             // segments per group (12*7 = 84 >= 81)

__global__ __launch_bounds__(128)
void phaseB_kernel(float* __restrict__ out) {
    __shared__ __align__(16) float mats[SPC * 100];   // 32.4 KB
    __shared__ __align__(16) float comb[NGB * 100];   // 4.8 KB

    const int tid = threadIdx.x;
    const int chain = blockIdx.x;

    // coalesced bulk load: 8100 floats = 2025 float4
    {
        const float4* src = reinterpret_cast<const float4*>(g_partials + chain * (SPC * 100));
        float4* dst = reinterpret_cast<float4*>(mats);
        for (int i = tid; i < (SPC * 100) / 4; i += 128) dst[i] = src[i];
    }
    __syncthreads();

    const int g = tid / MDIM;             // 0..11 groups; tid>=120 idle
    const int r = tid % MDIM;
    const bool active = (g < NGB);

    float P[MDIM];
    if (active) {
        const int s0 = g * GPB;
        const int s1 = min(s0 + GPB, SPC);
        // P = mats[s0]
        const float2* m2 = reinterpret_cast<const float2*>(mats + s0 * 100 + r * MDIM);
#pragma unroll
        for (int c2 = 0; c2 < 5; ++c2) {
            float2 v = m2[c2];
            P[2 * c2] = v.x; P[2 * c2 + 1] = v.y;
        }
        for (int si = s0 + 1; si < s1; ++si) {
            float Pn[MDIM];
            mm_row(P, mats + si * 100, Pn);
#pragma unroll
            for (int k = 0; k < MDIM; ++k) P[k] = Pn[k];
        }
        st_row(comb + g * 100 + r * MDIM, P);
    }
    __syncthreads();

    // pairwise tree reduction preserving order: cnt: 12 -> 6 -> 3 -> 2 -> 1
    int cnt = NGB;
    while (cnt > 1) {
        int half = cnt >> 1;
        bool odd = (cnt & 1) != 0;
        float R[MDIM];
        bool doP = active && (g < half);
        bool doCopy = active && odd && (g == half);
        if (doP) {
            float L[MDIM];
            const float2* l2 = reinterpret_cast<const float2*>(comb + (2 * g) * 100 + r * MDIM);
#pragma unroll
            for (int c2 = 0; c2 < 5; ++c2) {
                float2 v = l2[c2];
                L[2 * c2] = v.x; L[2 * c2 + 1] = v.y;
            }
            mm_row(L, comb + (2 * g + 1) * 100, R);
        } else if (doCopy) {
            const float2* l2 = reinterpret_cast<const float2*>(comb + (2 * g) * 100 + r * MDIM);
#pragma unroll
            for (int c2 = 0; c2 < 5; ++c2) {
                float2 v = l2[c2];
                R[2 * c2] = v.x; R[2 * c2 + 1] = v.y;
            }
        }
        __syncthreads();
        if (doP || doCopy) st_row(comb + g * 100 + r * MDIM, R);
        cnt = half + (odd ? 1 : 0);
        __syncthreads();
    }

    if (active && g == 0) {
        const float2* s2p = reinterpret_cast<const float2*>(comb + r * MDIM);
        float2* d2 = reinterpret_cast<float2*>(out + chain * 100 + r * MDIM);
#pragma unroll
        for (int c2 = 0; c2 < 5; ++c2) d2[c2] = s2p[c2];
    }
}

extern "C" void kernel_launch(void* const* d_in, const int* in_sizes, int n_in,
                              void* d_out, int out_size) {
    (void)in_sizes; (void)n_in; (void)out_size;
    const float* x = (const float*)d_in[0];   // (64, 2048, 8) f32
    const float* A = (const float*)d_in[1];   // (2, 8, 10, 10) f32
    float* out = (float*)d_out;               // (64, 2, 10, 10) f32

    // 128 chains * 27 warps = 3456 warps -> 432 blocks of 8 warps
    phaseA_kernel<<<432, 256>>>(x, A);
    phaseB_kernel<<<NCHAINS, 128>>>(out);
}